// round 1
// baseline (speedup 1.0000x reference)
#include <cuda_runtime.h>

#define NN 100000
#define NE 1600000

// ---------------- static device scratch (no allocations allowed) ----------------
__device__ int   g_outdeg[NN];
__device__ int   g_indeg[NN];
__device__ float g_nsrc[NN];
__device__ float g_ndst[NN];
__device__ int   g_rowptr[NN + 1];
__device__ int   g_cursor[NN];
__device__ int   g_bsum[128];
__device__ int   g_csr[NE];
__device__ float g_A[(size_t)NN * 128];   // matmul output / aggregation input
__device__ float g_B[(size_t)NN * 128];   // aggregation output / next-layer input

// ---------------- setup kernels ----------------
__global__ void k_zero() {
    int i = blockIdx.x * blockDim.x + threadIdx.x;
    if (i < NN) { g_outdeg[i] = 0; g_indeg[i] = 0; }
}

__global__ void k_count(const int* __restrict__ src, const int* __restrict__ dst) {
    int i = blockIdx.x * blockDim.x + threadIdx.x;
    if (i < NE) {
        atomicAdd(&g_outdeg[src[i]], 1);
        atomicAdd(&g_indeg[dst[i]], 1);
    }
}

__global__ void k_norm() {
    int i = blockIdx.x * blockDim.x + threadIdx.x;
    if (i < NN) {
        g_nsrc[i] = rsqrtf((float)max(g_outdeg[i], 1));
        g_ndst[i] = rsqrtf((float)max(g_indeg[i], 1));
    }
}

// Block-level exclusive scan of g_indeg into g_rowptr (1024 elems/block).
__global__ void k_scan1() {
    __shared__ int wsum[8];
    int t = threadIdx.x;
    int base = blockIdx.x * 1024 + t * 4;
    int v0 = 0, v1 = 0, v2 = 0, v3 = 0;
    if (base + 3 < NN) {
        int4 d = *(const int4*)&g_indeg[base];
        v0 = d.x; v1 = d.y; v2 = d.z; v3 = d.w;
    } else {
        if (base     < NN) v0 = g_indeg[base];
        if (base + 1 < NN) v1 = g_indeg[base + 1];
        if (base + 2 < NN) v2 = g_indeg[base + 2];
    }
    int tsum = v0 + v1 + v2 + v3;
    int lane = t & 31, w = t >> 5;
    int inc = tsum;
#pragma unroll
    for (int o = 1; o < 32; o <<= 1) {
        int y = __shfl_up_sync(0xffffffffu, inc, o);
        if (lane >= o) inc += y;
    }
    if (lane == 31) wsum[w] = inc;
    __syncthreads();
    if (t < 8) {
        int x = wsum[t];
#pragma unroll
        for (int o = 1; o < 8; o <<= 1) {
            int y = __shfl_up_sync(0xffu, x, o);
            if (t >= o) x += y;
        }
        wsum[t] = x;
    }
    __syncthreads();
    int excl = inc - tsum + (w ? wsum[w - 1] : 0);
    if (base     < NN) g_rowptr[base]     = excl;
    if (base + 1 < NN) g_rowptr[base + 1] = excl + v0;
    if (base + 2 < NN) g_rowptr[base + 2] = excl + v0 + v1;
    if (base + 3 < NN) g_rowptr[base + 3] = excl + v0 + v1 + v2;
    if (t == 255) g_bsum[blockIdx.x] = wsum[7];
}

__global__ void k_scan2(int nblk) {
    if (threadIdx.x == 0) {
        int run = 0;
        for (int i = 0; i < nblk; i++) { int v = g_bsum[i]; g_bsum[i] = run; run += v; }
    }
}

__global__ void k_scan3() {
    int i = blockIdx.x * blockDim.x + threadIdx.x;
    if (i < NN) {
        int v = g_rowptr[i] + g_bsum[i >> 10];
        g_rowptr[i] = v;
        g_cursor[i] = v;
    }
    if (i == 0) g_rowptr[NN] = NE;
}

__global__ void k_fill(const int* __restrict__ src, const int* __restrict__ dst) {
    int i = blockIdx.x * blockDim.x + threadIdx.x;
    if (i < NE) {
        int d = dst[i];
        int p = atomicAdd(&g_cursor[d], 1);
        g_csr[p] = src[i];
    }
}

// ---------------- dense matmul: g_A[n] = nsrc[n] * (X[n] @ W) ----------------
// X stride is always 128 (input dims). OUTD = 128 or 64.
// Tile: 64 nodes x OUTD cols per block, 256 threads, 4 cols/thread.
template <int OUTD>
__global__ void k_mm(const float* __restrict__ Xin, const float* __restrict__ W) {
    const float* X = Xin ? Xin : g_B;
    float* Y = g_A;
    constexpr int TC = OUTD / 4;        // thread-cols: 32 or 16
    constexpr int TR = 256 / TC;        // thread-rows: 8 or 16
    constexpr int NT = 64 / TR;         // nodes per thread: 8 or 4
    __shared__ float Xs[64][16];
    __shared__ float Ws[16][OUTD];
    int t = threadIdx.x;
    int tcol = t % TC;
    int trow = t / TC;
    int nodeBase = blockIdx.x * 64;
    float acc[NT][4];
#pragma unroll
    for (int i = 0; i < NT; i++) { acc[i][0] = acc[i][1] = acc[i][2] = acc[i][3] = 0.f; }

    int xr = t >> 2, xq = t & 3;
    for (int k0 = 0; k0 < 128; k0 += 16) {
        int gn = nodeBase + xr;
        float4 xv = make_float4(0.f, 0.f, 0.f, 0.f);
        if (gn < NN) xv = *(const float4*)&X[(size_t)gn * 128 + k0 + xq * 4];
        *(float4*)&Xs[xr][xq * 4] = xv;
        constexpr int WL = (16 * OUTD / 4) / 256;   // 2 or 1 float4 per thread
#pragma unroll
        for (int s = 0; s < WL; s++) {
            int idx = t + s * 256;
            ((float4*)Ws)[idx] = ((const float4*)(W + k0 * OUTD))[idx];
        }
        __syncthreads();
#pragma unroll
        for (int kk = 0; kk < 16; kk++) {
            float4 b = *(const float4*)&Ws[kk][tcol * 4];
#pragma unroll
            for (int i = 0; i < NT; i++) {
                float a = Xs[trow * NT + i][kk];
                acc[i][0] += a * b.x; acc[i][1] += a * b.y;
                acc[i][2] += a * b.z; acc[i][3] += a * b.w;
            }
        }
        __syncthreads();
    }
#pragma unroll
    for (int i = 0; i < NT; i++) {
        int n = nodeBase + trow * NT + i;
        if (n < NN) {
            float s = g_nsrc[n];
            float4 o = make_float4(acc[i][0] * s, acc[i][1] * s, acc[i][2] * s, acc[i][3] * s);
            *(float4*)&Y[(size_t)n * OUTD + tcol * 4] = o;
        }
    }
}

// ---------------- aggregation: g_B[n] = relu(ndst[n]*sum_{e in CSR(n)} g_A[csr[e]] + bias) ----
// Warp per destination node; gathers are L2-resident (51MB working set).
template <int OUTD>
__global__ void k_agg(const float* __restrict__ bias) {
    const float* T = g_A;
    float* Y = g_B;
    int gw = (blockIdx.x * blockDim.x + threadIdx.x) >> 5;
    int lane = threadIdx.x & 31;
    if (gw >= NN) return;
    int beg = g_rowptr[gw], end = g_rowptr[gw + 1];

    if (OUTD == 128) {
        float4 acc = make_float4(0.f, 0.f, 0.f, 0.f);
        int e = beg;
        for (; e + 4 <= end; e += 4) {
            int s0 = g_csr[e], s1 = g_csr[e + 1], s2 = g_csr[e + 2], s3 = g_csr[e + 3];
            float4 a0 = *(const float4*)&T[(size_t)s0 * 128 + lane * 4];
            float4 a1 = *(const float4*)&T[(size_t)s1 * 128 + lane * 4];
            float4 a2 = *(const float4*)&T[(size_t)s2 * 128 + lane * 4];
            float4 a3 = *(const float4*)&T[(size_t)s3 * 128 + lane * 4];
            acc.x += (a0.x + a1.x) + (a2.x + a3.x);
            acc.y += (a0.y + a1.y) + (a2.y + a3.y);
            acc.z += (a0.z + a1.z) + (a2.z + a3.z);
            acc.w += (a0.w + a1.w) + (a2.w + a3.w);
        }
        for (; e < end; e++) {
            int s = g_csr[e];
            float4 a = *(const float4*)&T[(size_t)s * 128 + lane * 4];
            acc.x += a.x; acc.y += a.y; acc.z += a.z; acc.w += a.w;
        }
        float nd = g_ndst[gw];
        float4 bb = *(const float4*)&bias[lane * 4];
        float4 o = make_float4(fmaxf(acc.x * nd + bb.x, 0.f),
                               fmaxf(acc.y * nd + bb.y, 0.f),
                               fmaxf(acc.z * nd + bb.z, 0.f),
                               fmaxf(acc.w * nd + bb.w, 0.f));
        *(float4*)&Y[(size_t)gw * 128 + lane * 4] = o;
    } else {
        float2 acc = make_float2(0.f, 0.f);
        int e = beg;
        for (; e + 4 <= end; e += 4) {
            int s0 = g_csr[e], s1 = g_csr[e + 1], s2 = g_csr[e + 2], s3 = g_csr[e + 3];
            float2 a0 = *(const float2*)&T[(size_t)s0 * 64 + lane * 2];
            float2 a1 = *(const float2*)&T[(size_t)s1 * 64 + lane * 2];
            float2 a2 = *(const float2*)&T[(size_t)s2 * 64 + lane * 2];
            float2 a3 = *(const float2*)&T[(size_t)s3 * 64 + lane * 2];
            acc.x += (a0.x + a1.x) + (a2.x + a3.x);
            acc.y += (a0.y + a1.y) + (a2.y + a3.y);
        }
        for (; e < end; e++) {
            int s = g_csr[e];
            float2 a = *(const float2*)&T[(size_t)s * 64 + lane * 2];
            acc.x += a.x; acc.y += a.y;
        }
        float nd = g_ndst[gw];
        float2 bb = *(const float2*)&bias[lane * 2];
        float2 o = make_float2(fmaxf(acc.x * nd + bb.x, 0.f),
                               fmaxf(acc.y * nd + bb.y, 0.f));
        *(float2*)&Y[(size_t)gw * 64 + lane * 2] = o;
    }
}

// ---------------- log_softmax over 64 cols, warp per node ----------------
__global__ void k_lsm(float* __restrict__ out) {
    int gw = (blockIdx.x * blockDim.x + threadIdx.x) >> 5;
    int lane = threadIdx.x & 31;
    if (gw >= NN) return;
    float2 v = *(const float2*)&g_B[(size_t)gw * 64 + lane * 2];
    float m = fmaxf(v.x, v.y);
#pragma unroll
    for (int o = 16; o; o >>= 1) m = fmaxf(m, __shfl_xor_sync(0xffffffffu, m, o));
    float s = expf(v.x - m) + expf(v.y - m);
#pragma unroll
    for (int o = 16; o; o >>= 1) s += __shfl_xor_sync(0xffffffffu, s, o);
    float ls = logf(s);
    float2 o2 = make_float2(v.x - m - ls, v.y - m - ls);
    *(float2*)&out[(size_t)gw * 64 + lane * 2] = o2;
}

// ---------------- launch ----------------
extern "C" void kernel_launch(void* const* d_in, const int* in_sizes, int n_in,
                              void* d_out, int out_size) {
    const float* feats = (const float*)d_in[0];
    const float* W0 = (const float*)d_in[1];
    const float* b0 = (const float*)d_in[2];
    const float* W1 = (const float*)d_in[3];
    const float* b1 = (const float*)d_in[4];
    const float* W2 = (const float*)d_in[5];
    const float* b2 = (const float*)d_in[6];
    const int* src = (const int*)d_in[7];
    const int* dst = (const int*)d_in[8];
    float* out = (float*)d_out;

    const int nodeGrid = (NN + 255) / 256;
    const int edgeGrid = (NE + 255) / 256;
    const int scanBlk = (NN + 1023) / 1024;
    const int mmGrid = (NN + 63) / 64;
    const int warpGrid = (NN * 32 + 255) / 256;

    // graph structure + norms (recomputed every call: deterministic, no caching)
    k_zero<<<nodeGrid, 256>>>();
    k_count<<<edgeGrid, 256>>>(src, dst);
    k_norm<<<nodeGrid, 256>>>();
    k_scan1<<<scanBlk, 256>>>();
    k_scan2<<<1, 32>>>(scanBlk);
    k_scan3<<<nodeGrid, 256>>>();
    k_fill<<<edgeGrid, 256>>>(src, dst);

    // layer 0: tmp = nsrc*(feats@W0); h = relu(ndst*Agg(tmp) + b0)
    k_mm<128><<<mmGrid, 256>>>(feats, W0);
    k_agg<128><<<warpGrid, 256>>>(b0);
    // layer 1
    k_mm<128><<<mmGrid, 256>>>(nullptr, W1);
    k_agg<128><<<warpGrid, 256>>>(b1);
    // layer 2 (W commuted past aggregation: aggregate 64-wide, halves traffic)
    k_mm<64><<<mmGrid, 256>>>(nullptr, W2);
    k_agg<64><<<warpGrid, 256>>>(b2);
    // log_softmax
    k_lsm<<<warpGrid, 256>>>(out);
}

// round 2
// speedup vs baseline: 1.0821x; 1.0821x over previous
#include <cuda_runtime.h>

#define NN 100000
#define NE 1600000

// ---------------- static device scratch (no allocations allowed) ----------------
__device__ int   g_outdeg[NN];
__device__ int   g_indeg[NN];
__device__ float g_nsrc[NN];
__device__ float g_ndst[NN];
__device__ int   g_rowptr[NN + 1];
__device__ int   g_cursor[NN];
__device__ int   g_bsum[128];
__device__ int   g_csr[NE];
__device__ float g_A[(size_t)NN * 128];   // matmul output / aggregation input
__device__ float g_B[(size_t)NN * 128];   // aggregation output / next-layer input

// ---------------- setup kernels ----------------
__global__ void k_zero() {
    int i = blockIdx.x * blockDim.x + threadIdx.x;
    if (i < NN) { g_outdeg[i] = 0; g_indeg[i] = 0; }
}

__global__ void k_count(const int* __restrict__ src, const int* __restrict__ dst) {
    int i = blockIdx.x * blockDim.x + threadIdx.x;
    if (i < NE) {
        atomicAdd(&g_outdeg[src[i]], 1);
        atomicAdd(&g_indeg[dst[i]], 1);
    }
}

__global__ void k_norm() {
    int i = blockIdx.x * blockDim.x + threadIdx.x;
    if (i < NN) {
        g_nsrc[i] = rsqrtf((float)max(g_outdeg[i], 1));
        g_ndst[i] = rsqrtf((float)max(g_indeg[i], 1));
    }
}

// Block-level exclusive scan of g_indeg into g_rowptr (1024 elems/block).
__global__ void k_scan1() {
    __shared__ int wsum[8];
    int t = threadIdx.x;
    int base = blockIdx.x * 1024 + t * 4;
    int v0 = 0, v1 = 0, v2 = 0, v3 = 0;
    if (base + 3 < NN) {
        int4 d = *(const int4*)&g_indeg[base];
        v0 = d.x; v1 = d.y; v2 = d.z; v3 = d.w;
    } else {
        if (base     < NN) v0 = g_indeg[base];
        if (base + 1 < NN) v1 = g_indeg[base + 1];
        if (base + 2 < NN) v2 = g_indeg[base + 2];
    }
    int tsum = v0 + v1 + v2 + v3;
    int lane = t & 31, w = t >> 5;
    int inc = tsum;
#pragma unroll
    for (int o = 1; o < 32; o <<= 1) {
        int y = __shfl_up_sync(0xffffffffu, inc, o);
        if (lane >= o) inc += y;
    }
    if (lane == 31) wsum[w] = inc;
    __syncthreads();
    if (t < 8) {
        int x = wsum[t];
#pragma unroll
        for (int o = 1; o < 8; o <<= 1) {
            int y = __shfl_up_sync(0xffu, x, o);
            if (t >= o) x += y;
        }
        wsum[t] = x;
    }
    __syncthreads();
    int excl = inc - tsum + (w ? wsum[w - 1] : 0);
    if (base     < NN) g_rowptr[base]     = excl;
    if (base + 1 < NN) g_rowptr[base + 1] = excl + v0;
    if (base + 2 < NN) g_rowptr[base + 2] = excl + v0 + v1;
    if (base + 3 < NN) g_rowptr[base + 3] = excl + v0 + v1 + v2;
    if (t == 255) g_bsum[blockIdx.x] = wsum[7];
}

__global__ void k_scan2(int nblk) {
    if (threadIdx.x == 0) {
        int run = 0;
        for (int i = 0; i < nblk; i++) { int v = g_bsum[i]; g_bsum[i] = run; run += v; }
    }
}

__global__ void k_scan3() {
    int i = blockIdx.x * blockDim.x + threadIdx.x;
    if (i < NN) {
        int v = g_rowptr[i] + g_bsum[i >> 10];
        g_rowptr[i] = v;
        g_cursor[i] = v;
    }
    if (i == 0) g_rowptr[NN] = NE;
}

__global__ void k_fill(const int* __restrict__ src, const int* __restrict__ dst) {
    int i = blockIdx.x * blockDim.x + threadIdx.x;
    if (i < NE) {
        int d = dst[i];
        int p = atomicAdd(&g_cursor[d], 1);
        g_csr[p] = src[i];
    }
}

// ---------------- tf32 helpers ----------------
__device__ __forceinline__ void split_tf32(float x, unsigned& hi, unsigned& lo) {
    unsigned h;
    asm("cvt.rna.tf32.f32 %0, %1;" : "=r"(h) : "f"(x));
    float hf = __uint_as_float(h);
    float l = x - hf;
    unsigned lu;
    asm("cvt.rna.tf32.f32 %0, %1;" : "=r"(lu) : "f"(l));
    hi = h; lo = lu;
}

__device__ __forceinline__ void mma8(float* c, const unsigned* a, unsigned b0, unsigned b1) {
    asm volatile(
        "mma.sync.aligned.m16n8k8.row.col.f32.tf32.tf32.f32 "
        "{%0,%1,%2,%3}, {%4,%5,%6,%7}, {%8,%9}, {%0,%1,%2,%3};"
        : "+f"(c[0]), "+f"(c[1]), "+f"(c[2]), "+f"(c[3])
        : "r"(a[0]), "r"(a[1]), "r"(a[2]), "r"(a[3]), "r"(b0), "r"(b1));
}

// ---------------- tensor-core matmul: g_A[n] = nsrc[n] * (X[n] @ W) ----------------
// 3xTF32 split recovers fp32 precision. Block: 128 nodes x OUTD cols, 256 threads.
template <int OUTD>
__global__ void k_mm_tc(const float* __restrict__ Xin, const float* __restrict__ W) {
    const float* X = Xin ? Xin : g_B;
    constexpr int WN = (OUTD == 128) ? 2 : 1;   // warps along N
    constexpr int WM = 8 / WN;                  // warps along M: 4 or 8
    constexpr int MW = 128 / WM;                // rows per warp: 32 or 16
    constexpr int MT = MW / 16;                 // m16 tiles per warp: 2 or 1
    constexpr int NT = 8;                       // n8 tiles per warp (64 cols)
    constexpr int WS = OUTD + 8;                // padded W stride (bank-conflict-free)
    __shared__ float Xs[128 * 36];              // 128 x 32, stride 36
    __shared__ float Ws[32 * WS];               // 32 x OUTD

    int t = threadIdx.x;
    int lane = t & 31, warp = t >> 5;
    int warpM = warp / WN, warpN = warp % WN;
    int nodeBase = blockIdx.x * 128;
    int gid = lane >> 2, tig = lane & 3;        // mma group id / thread-in-group

    float acc[MT][NT][4] = {};

    for (int k0 = 0; k0 < 128; k0 += 32) {
        // Load X chunk: 128 rows x 32 cols. 2 threads per row, 4 float4 each.
        {
            int r = t >> 1, q = t & 1;
            int gn = nodeBase + r;
#pragma unroll
            for (int j = 0; j < 4; j++) {
                float4 v = make_float4(0.f, 0.f, 0.f, 0.f);
                if (gn < NN) v = *(const float4*)&X[(size_t)gn * 128 + k0 + q * 16 + j * 4];
                *(float4*)&Xs[r * 36 + q * 16 + j * 4] = v;
            }
        }
        // Load W chunk: 32 rows x OUTD cols.
        {
            constexpr int WV = 32 * OUTD / 4 / 256;  // 4 or 2 float4 per thread
#pragma unroll
            for (int s = 0; s < WV; s++) {
                int idx = t + s * 256;
                int row = idx / (OUTD / 4), c4 = idx % (OUTD / 4);
                float4 v = *(const float4*)&W[(size_t)(k0 + row) * OUTD + c4 * 4];
                *(float4*)&Ws[row * WS + c4 * 4] = v;
            }
        }
        __syncthreads();
#pragma unroll
        for (int ks = 0; ks < 4; ks++) {
            unsigned ahi[MT][4], alo[MT][4];
#pragma unroll
            for (int mt = 0; mt < MT; mt++) {
                int r = warpM * MW + mt * 16 + gid;
                int c = ks * 8 + tig;
                split_tf32(Xs[r * 36 + c],           ahi[mt][0], alo[mt][0]);
                split_tf32(Xs[(r + 8) * 36 + c],     ahi[mt][1], alo[mt][1]);
                split_tf32(Xs[r * 36 + c + 4],       ahi[mt][2], alo[mt][2]);
                split_tf32(Xs[(r + 8) * 36 + c + 4], ahi[mt][3], alo[mt][3]);
            }
#pragma unroll
            for (int nt = 0; nt < NT; nt++) {
                int row = ks * 8 + tig;
                int n = warpN * 64 + nt * 8 + gid;
                unsigned bh0, bl0, bh1, bl1;
                split_tf32(Ws[row * WS + n],       bh0, bl0);
                split_tf32(Ws[(row + 4) * WS + n], bh1, bl1);
#pragma unroll
                for (int mt = 0; mt < MT; mt++) {
                    mma8(acc[mt][nt], alo[mt], bh0, bh1);   // Alo*Bhi
                    mma8(acc[mt][nt], ahi[mt], bl0, bl1);   // Ahi*Blo
                    mma8(acc[mt][nt], ahi[mt], bh0, bh1);   // Ahi*Bhi
                }
            }
        }
        __syncthreads();
    }
    // Epilogue: scale by nsrc, write float2 pairs.
#pragma unroll
    for (int mt = 0; mt < MT; mt++) {
        int r0 = nodeBase + warpM * MW + mt * 16 + gid;
        int r1 = r0 + 8;
        float s0 = (r0 < NN) ? g_nsrc[r0] : 0.f;
        float s1 = (r1 < NN) ? g_nsrc[r1] : 0.f;
#pragma unroll
        for (int nt = 0; nt < NT; nt++) {
            int cc = warpN * 64 + nt * 8 + 2 * tig;
            if (r0 < NN) {
                float2 v = make_float2(acc[mt][nt][0] * s0, acc[mt][nt][1] * s0);
                *(float2*)&g_A[(size_t)r0 * OUTD + cc] = v;
            }
            if (r1 < NN) {
                float2 v = make_float2(acc[mt][nt][2] * s1, acc[mt][nt][3] * s1);
                *(float2*)&g_A[(size_t)r1 * OUTD + cc] = v;
            }
        }
    }
}

// ---------------- aggregation (128-wide): g_B[n] = relu(ndst[n]*sum + bias) ----------------
__global__ void k_agg128(const float* __restrict__ bias) {
    const float* T = g_A;
    float* Y = g_B;
    int gw = (blockIdx.x * blockDim.x + threadIdx.x) >> 5;
    int lane = threadIdx.x & 31;
    if (gw >= NN) return;
    int beg = g_rowptr[gw], end = g_rowptr[gw + 1];

    float4 acc = make_float4(0.f, 0.f, 0.f, 0.f);
    int e = beg;
    for (; e + 4 <= end; e += 4) {
        int s0 = g_csr[e], s1 = g_csr[e + 1], s2 = g_csr[e + 2], s3 = g_csr[e + 3];
        float4 a0 = *(const float4*)&T[(size_t)s0 * 128 + lane * 4];
        float4 a1 = *(const float4*)&T[(size_t)s1 * 128 + lane * 4];
        float4 a2 = *(const float4*)&T[(size_t)s2 * 128 + lane * 4];
        float4 a3 = *(const float4*)&T[(size_t)s3 * 128 + lane * 4];
        acc.x += (a0.x + a1.x) + (a2.x + a3.x);
        acc.y += (a0.y + a1.y) + (a2.y + a3.y);
        acc.z += (a0.z + a1.z) + (a2.z + a3.z);
        acc.w += (a0.w + a1.w) + (a2.w + a3.w);
    }
    for (; e < end; e++) {
        int s = g_csr[e];
        float4 a = *(const float4*)&T[(size_t)s * 128 + lane * 4];
        acc.x += a.x; acc.y += a.y; acc.z += a.z; acc.w += a.w;
    }
    float nd = g_ndst[gw];
    float4 bb = *(const float4*)&bias[lane * 4];
    float4 o = make_float4(fmaxf(acc.x * nd + bb.x, 0.f),
                           fmaxf(acc.y * nd + bb.y, 0.f),
                           fmaxf(acc.z * nd + bb.z, 0.f),
                           fmaxf(acc.w * nd + bb.w, 0.f));
    *(float4*)&Y[(size_t)gw * 128 + lane * 4] = o;
}

// ---------------- final aggregation (64-wide) fused with relu + log_softmax ----------------
__global__ void k_agg_lsm(const float* __restrict__ bias, float* __restrict__ out) {
    const float* T = g_A;
    int gw = (blockIdx.x * blockDim.x + threadIdx.x) >> 5;
    int lane = threadIdx.x & 31;
    if (gw >= NN) return;
    int beg = g_rowptr[gw], end = g_rowptr[gw + 1];

    float2 acc = make_float2(0.f, 0.f);
    int e = beg;
    for (; e + 4 <= end; e += 4) {
        int s0 = g_csr[e], s1 = g_csr[e + 1], s2 = g_csr[e + 2], s3 = g_csr[e + 3];
        float2 a0 = *(const float2*)&T[(size_t)s0 * 64 + lane * 2];
        float2 a1 = *(const float2*)&T[(size_t)s1 * 64 + lane * 2];
        float2 a2 = *(const float2*)&T[(size_t)s2 * 64 + lane * 2];
        float2 a3 = *(const float2*)&T[(size_t)s3 * 64 + lane * 2];
        acc.x += (a0.x + a1.x) + (a2.x + a3.x);
        acc.y += (a0.y + a1.y) + (a2.y + a3.y);
    }
    for (; e < end; e++) {
        int s = g_csr[e];
        float2 a = *(const float2*)&T[(size_t)s * 64 + lane * 2];
        acc.x += a.x; acc.y += a.y;
    }
    float nd = g_ndst[gw];
    float2 bb = *(const float2*)&bias[lane * 2];
    float vx = fmaxf(acc.x * nd + bb.x, 0.f);
    float vy = fmaxf(acc.y * nd + bb.y, 0.f);

    // log_softmax over the 64 values held by this warp (2 per lane)
    float m = fmaxf(vx, vy);
#pragma unroll
    for (int o = 16; o; o >>= 1) m = fmaxf(m, __shfl_xor_sync(0xffffffffu, m, o));
    float s = expf(vx - m) + expf(vy - m);
#pragma unroll
    for (int o = 16; o; o >>= 1) s += __shfl_xor_sync(0xffffffffu, s, o);
    float ls = logf(s);
    float2 o2 = make_float2(vx - m - ls, vy - m - ls);
    *(float2*)&out[(size_t)gw * 64 + lane * 2] = o2;
}

// ---------------- launch ----------------
extern "C" void kernel_launch(void* const* d_in, const int* in_sizes, int n_in,
                              void* d_out, int out_size) {
    const float* feats = (const float*)d_in[0];
    const float* W0 = (const float*)d_in[1];
    const float* b0 = (const float*)d_in[2];
    const float* W1 = (const float*)d_in[3];
    const float* b1 = (const float*)d_in[4];
    const float* W2 = (const float*)d_in[5];
    const float* b2 = (const float*)d_in[6];
    const int* src = (const int*)d_in[7];
    const int* dst = (const int*)d_in[8];
    float* out = (float*)d_out;

    const int nodeGrid = (NN + 255) / 256;
    const int edgeGrid = (NE + 255) / 256;
    const int scanBlk = (NN + 1023) / 1024;
    const int mmGrid = (NN + 127) / 128;
    const int warpGrid = (NN * 32 + 255) / 256;

    // graph structure + norms
    k_zero<<<nodeGrid, 256>>>();
    k_count<<<edgeGrid, 256>>>(src, dst);
    k_norm<<<nodeGrid, 256>>>();
    k_scan1<<<scanBlk, 256>>>();
    k_scan2<<<1, 32>>>(scanBlk);
    k_scan3<<<nodeGrid, 256>>>();
    k_fill<<<edgeGrid, 256>>>(src, dst);

    // layer 0: tmp = nsrc*(feats@W0); h = relu(ndst*Agg(tmp) + b0)
    k_mm_tc<128><<<mmGrid, 256>>>(feats, W0);
    k_agg128<<<warpGrid, 256>>>(b0);
    // layer 1
    k_mm_tc<128><<<mmGrid, 256>>>(nullptr, W1);
    k_agg128<<<warpGrid, 256>>>(b1);
    // layer 2 (W commuted past aggregation: aggregate 64-wide) + fused log_softmax
    k_mm_tc<64><<<mmGrid, 256>>>(nullptr, W2);
    k_agg_lsm<<<warpGrid, 256>>>(b2, out);
}